// round 7
// baseline (speedup 1.0000x reference)
#include <cuda_runtime.h>
#include <cuda_fp16.h>
#include <cstdint>
#include <mma.h>
#include <math.h>

using namespace nvcuda;

// ---------------- constants ----------------
#define SEQ      2048
#define DMODEL   2048
#define HEADS    16
#define HDIM     128
#define INNER    8192
#define LN_EPS   1e-5f

// ---------------- scratch (static device memory; no allocations) ----------
__device__ __half g_c[SEQ * 3 * DMODEL];     // QKV (half)
__device__ __half g_attn[SEQ * DMODEL];      // attention out (half)
__device__ float  g_res1[SEQ * DMODEL];      // x + proj(attn)
__device__ float  g_h1[SEQ * DMODEL];        // LN1 out fp32 (residual)
__device__ __half g_h1h[SEQ * DMODEL];       // LN1 out half (GEMM A)
__device__ __half g_ff[SEQ * INNER];         // gelu(...) half
__device__ float  g_res2[SEQ * DMODEL];
__device__ __half g_xh[SEQ * DMODEL];        // x half
__device__ __half g_Cwh[DMODEL * 3 * DMODEL];
__device__ __half g_linh[DMODEL * DMODEL];
__device__ __half g_ff1h[DMODEL * INNER];
__device__ __half g_ff2h[INNER * DMODEL];

// ---------------- helpers ----------------
__device__ __forceinline__ float gelu_f(float v) {
    return 0.5f * v * (1.0f + erff(v * 0.7071067811865476f));
}
__device__ __forceinline__ uint32_t smem_u32(const void* p) {
    uint32_t a;
    asm("{ .reg .u64 t; cvta.to.shared.u64 t, %1; cvt.u32.u64 %0, t; }"
        : "=r"(a) : "l"(p));
    return a;
}
__device__ __forceinline__ void cp16(uint32_t dst, const void* src) {
    asm volatile("cp.async.cg.shared.global [%0], [%1], 16;" :: "r"(dst), "l"(src));
}
#define CP_COMMIT() asm volatile("cp.async.commit_group;" ::: "memory")
#define CP_WAIT(n)  asm volatile("cp.async.wait_group %0;" :: "n"(n) : "memory")

// ================= float -> half conversion =================================
__global__ void __launch_bounds__(256)
f2h_kernel(const float* __restrict__ in, __half* __restrict__ out, int n4)
{
    int i = blockIdx.x * 256 + threadIdx.x;
    int stride = gridDim.x * 256;
    for (; i < n4; i += stride) {
        float4 v = ((const float4*)in)[i];
        __half2 p0 = __floats2half2_rn(v.x, v.y);
        __half2 p1 = __floats2half2_rn(v.z, v.w);
        uint2 u;
        u.x = *(uint32_t*)&p0;
        u.y = *(uint32_t*)&p1;
        ((uint2*)out)[i] = u;
    }
}

// ================= FP16 WMMA GEMM, 128x256x64 CTA tiles =====================
// C[M,N] = A[M,K] @ B[K,N] + bias (+res / gelu). A,B half; accum fp32.
// 256 threads = 8 warps, warp grid 2(M) x 4(N), warp tile 64x64 (cf[4][4]).
#define ALD 72      // halves/row (144 B)
#define BLD 264     // halves/row (528 B)
#define A_STAGE (128 * 144)                 // 18432 B
#define B_STAGE (64 * 528)                  // 33792 B
#define GSTAGES 3
#define STAGE_BYTES (A_STAGE + B_STAGE)     // 52224
#define GEMM_SMEM   (GSTAGES * STAGE_BYTES) // 156672

enum { EPI_BIAS = 0, EPI_BIAS_RES = 1, EPI_BIAS_GELU = 2 };

template <int EPI, bool OUTH>
__global__ void __launch_bounds__(256, 1)
gemm_fp16(const __half* __restrict__ A, const __half* __restrict__ B,
          const float* __restrict__ bias, const float* __restrict__ res,
          void* __restrict__ Cout, int M, int N, int K)
{
    extern __shared__ char smg[];
    const uint32_t sbase = smem_u32(smg);

    const int tid  = threadIdx.x;
    const int bm   = blockIdx.y;
    const int bn   = blockIdx.x;
    const int warp = tid >> 5;
    const int wm   = warp & 1;     // 2 strips of 64 rows
    const int wn   = warp >> 1;    // 4 strips of 64 cols

    wmma::fragment<wmma::accumulator, 16, 16, 16, float> cf[4][4];
    #pragma unroll
    for (int i = 0; i < 4; ++i)
        #pragma unroll
        for (int j = 0; j < 4; ++j)
            wmma::fill_fragment(cf[i][j], 0.0f);

    const __half* Aptr = A + (size_t)(bm * 128) * K;
    const __half* Bptr = B + (size_t)bn * 256;
    const int nT = K >> 6;

    // A: 128 rows x 64 half = 8 chunks/row (1024 chunks, 4/thread)
    // B: 64 rows x 256 half = 32 chunks/row (2048 chunks, 8/thread)
    auto load_stage = [&](int s, int kt) {
        uint32_t sa = sbase + s * STAGE_BYTES;
        uint32_t sb = sa + A_STAGE;
        #pragma unroll
        for (int i = 0; i < 4; ++i) {
            int idx = tid + i * 256;
            int r = idx >> 3, c = idx & 7;
            cp16(sa + r * 144 + c * 16, Aptr + (size_t)r * K + kt * 64 + c * 8);
        }
        #pragma unroll
        for (int i = 0; i < 8; ++i) {
            int idx = tid + i * 256;
            int r = idx >> 5, c = idx & 31;
            cp16(sb + r * 528 + c * 16, Bptr + (size_t)(kt * 64 + r) * N + c * 8);
        }
    };

    load_stage(0, 0); CP_COMMIT();
    load_stage(1, 1); CP_COMMIT();

    for (int kt = 0; kt < nT; ++kt) {
        const int s = kt % GSTAGES;
        if (kt + 2 < nT) { load_stage((kt + 2) % GSTAGES, kt + 2); CP_COMMIT(); CP_WAIT(2); }
        else if (kt + 1 < nT) { CP_WAIT(1); }
        else { CP_WAIT(0); }
        __syncthreads();

        const __half* As = (const __half*)(smg + s * STAGE_BYTES);
        const __half* Bs = As + A_STAGE / 2;
        #pragma unroll
        for (int ks = 0; ks < 4; ++ks) {
            wmma::fragment<wmma::matrix_a, 16, 16, 16, __half, wmma::row_major> af[4];
            wmma::fragment<wmma::matrix_b, 16, 16, 16, __half, wmma::row_major> bf[4];
            #pragma unroll
            for (int i = 0; i < 4; ++i)
                wmma::load_matrix_sync(af[i], As + (wm * 64 + i * 16) * ALD + ks * 16, ALD);
            #pragma unroll
            for (int j = 0; j < 4; ++j)
                wmma::load_matrix_sync(bf[j], Bs + (ks * 16) * BLD + wn * 64 + j * 16, BLD);
            #pragma unroll
            for (int i = 0; i < 4; ++i)
                #pragma unroll
                for (int j = 0; j < 4; ++j)
                    wmma::mma_sync(cf[i][j], af[i], bf[j], cf[i][j]);
        }
        __syncthreads();
    }

    float* Cs = (float*)smg;  // 128 x 256 fp32 staging (128 KB)
    #pragma unroll
    for (int i = 0; i < 4; ++i)
        #pragma unroll
        for (int j = 0; j < 4; ++j)
            wmma::store_matrix_sync(Cs + (wm * 64 + i * 16) * 256 + wn * 64 + j * 16,
                                    cf[i][j], 256, wmma::mem_row_major);
    __syncthreads();

    #pragma unroll
    for (int it = 0; it < 32; ++it) {
        int f4 = tid + it * 256;          // 8192 float4
        int r = f4 >> 6, c4 = f4 & 63;
        float4 v = ((float4*)Cs)[f4];
        int gn = bn * 256 + c4 * 4;
        float4 bv = *(const float4*)(bias + gn);
        v.x += bv.x; v.y += bv.y; v.z += bv.z; v.w += bv.w;
        size_t goff = (size_t)(bm * 128 + r) * N + gn;
        if (EPI == EPI_BIAS_RES) {
            float4 rv = *(const float4*)(res + goff);
            v.x += rv.x; v.y += rv.y; v.z += rv.z; v.w += rv.w;
        }
        if (EPI == EPI_BIAS_GELU) {
            v.x = gelu_f(v.x); v.y = gelu_f(v.y);
            v.z = gelu_f(v.z); v.w = gelu_f(v.w);
        }
        if (OUTH) {
            __half2 p0 = __floats2half2_rn(v.x, v.y);
            __half2 p1 = __floats2half2_rn(v.z, v.w);
            uint2 u;
            u.x = *(uint32_t*)&p0;
            u.y = *(uint32_t*)&p1;
            *(uint2*)((__half*)Cout + goff) = u;
        } else {
            *(float4*)((float*)Cout + goff) = v;
        }
    }
}

// ================= causal flash attention, fp16 WMMA, cp.async KV ==========
// c half [SEQ, 3*DMODEL]. Block (qt, h), 256 thr, BQ=BK=64, KV double-buffered.
#define QLDH 136                              // halves (272B rows)
#define SLDF 68                               // fp32
#define PLDH 72                               // halves
#define OFF_Q   0                             // 64*272 = 17408 B
#define OFF_K   17408                         // 2 x 17408
#define OFF_V   (OFF_K + 2 * 17408)
#define OFF_S   (OFF_V + 2 * 17408)           // 64*68*4 = 17408 B
#define OFF_P   (OFF_S + 17408)               // 64*72*2 = 9216 B
#define OFF_RP  (OFF_P + 9216)                // 256*4
#define OFF_M   (OFF_RP + 1024)               // 64*4
#define OFF_L   (OFF_M + 256)
#define OFF_A   (OFF_L + 256)
#define ATT_SMEM (OFF_A + 256)

__global__ void __launch_bounds__(256)
attn_kernel(const __half* __restrict__ c, __half* __restrict__ out)
{
    const int h  = blockIdx.y;
    const int qt = gridDim.x - 1 - blockIdx.x;   // heavy tiles first

    extern __shared__ char smg[];
    const uint32_t sbase = smem_u32(smg);
    __half* Qs   = (__half*)(smg + OFF_Q);
    float*  S    = (float*)(smg + OFF_S);
    __half* P    = (__half*)(smg + OFF_P);
    float* rowpat = (float*)(smg + OFF_RP);
    float* mrow  = (float*)(smg + OFF_M);
    float* lrow  = (float*)(smg + OFF_L);
    float* arow  = (float*)(smg + OFF_A);

    const int tid  = threadIdx.x;
    const int warp = tid >> 5;
    const int wm   = warp & 3;
    const int wn   = warp >> 2;

    auto load_kv = [&](int buf, int j) {
        uint32_t kb = sbase + OFF_K + buf * 17408;
        uint32_t vb = sbase + OFF_V + buf * 17408;
        const __half* base = c + (size_t)(j * 64) * (3 * DMODEL) + h * HDIM;
        #pragma unroll
        for (int i = 0; i < 4; ++i) {
            int idx = tid + i * 256;
            int r = idx >> 4, cc = idx & 15;
            const __half* rp = base + (size_t)r * (3 * DMODEL) + cc * 8;
            cp16(kb + r * 272 + cc * 16, rp + DMODEL);
            cp16(vb + r * 272 + cc * 16, rp + 2 * DMODEL);
        }
    };

    load_kv(0, 0); CP_COMMIT();

    #pragma unroll
    for (int i = 0; i < 4; ++i) {
        int idx = tid + i * 256;
        int r = idx >> 4, cc = idx & 15;
        *(uint4*)((char*)Qs + r * 272 + cc * 16) =
            *(const uint4*)(c + (size_t)(qt * 64 + r) * (3 * DMODEL) + h * HDIM + cc * 8);
    }
    rowpat[tid] = (float)(tid >> 4);
    if (tid < 64) { mrow[tid] = -1e30f; lrow[tid] = 0.0f; }
    __syncthreads();

    wmma::fragment<wmma::accumulator, 16, 16, 16, float> rowf;
    wmma::load_matrix_sync(rowf, rowpat, 16, wmma::mem_row_major);
    int rowid[8];
    #pragma unroll
    for (int e = 0; e < 8; ++e) rowid[e] = (int)rowf.x[e];

    wmma::fragment<wmma::accumulator, 16, 16, 16, float> of[4];
    #pragma unroll
    for (int j = 0; j < 4; ++j) wmma::fill_fragment(of[j], 0.0f);

    const float scale = 0.022097086912079608f;  // 1/sqrt(2048)
    const int srow = tid >> 2, sq = tid & 3;

    for (int j = 0; j <= qt; ++j) {
        if (j < qt) { load_kv((j + 1) & 1, j + 1); CP_COMMIT(); CP_WAIT(1); }
        else        { CP_WAIT(0); }
        __syncthreads();

        const __half* Ks = (const __half*)(smg + OFF_K + (j & 1) * 17408);
        const __half* Vs = (const __half*)(smg + OFF_V + (j & 1) * 17408);

        // S = Q @ K^T : each warp 16x32
        {
            wmma::fragment<wmma::accumulator, 16, 16, 16, float> sf[2];
            wmma::fill_fragment(sf[0], 0.0f);
            wmma::fill_fragment(sf[1], 0.0f);
            #pragma unroll
            for (int ks = 0; ks < 8; ++ks) {
                wmma::fragment<wmma::matrix_a, 16, 16, 16, __half, wmma::row_major> af;
                wmma::load_matrix_sync(af, Qs + (wm * 16) * QLDH + ks * 16, QLDH);
                #pragma unroll
                for (int jj = 0; jj < 2; ++jj) {
                    wmma::fragment<wmma::matrix_b, 16, 16, 16, __half, wmma::col_major> bf;
                    wmma::load_matrix_sync(bf, Ks + (wn * 32 + jj * 16) * QLDH + ks * 16, QLDH);
                    wmma::mma_sync(sf[jj], af, bf, sf[jj]);
                }
            }
            #pragma unroll
            for (int jj = 0; jj < 2; ++jj)
                wmma::store_matrix_sync(S + (wm * 16) * SLDF + wn * 32 + jj * 16,
                                        sf[jj], SLDF, wmma::mem_row_major);
        }
        __syncthreads();

        // online softmax: 4 threads/row, quad shuffles; P half
        {
            const bool diag = (j == qt);
            float m_old = mrow[srow];
            float mx = m_old;
            float sv[16];
            #pragma unroll
            for (int k = 0; k < 16; ++k) {
                int kcol = sq * 16 + k;
                float v = S[srow * SLDF + kcol] * scale;
                if (diag && kcol > srow) v = -1e30f;
                sv[k] = v;
                mx = fmaxf(mx, v);
            }
            mx = fmaxf(mx, __shfl_xor_sync(0xffffffffu, mx, 1));
            mx = fmaxf(mx, __shfl_xor_sync(0xffffffffu, mx, 2));
            float sum = 0.0f;
            #pragma unroll
            for (int k = 0; k < 16; ++k) {
                float p = __expf(sv[k] - mx);
                sum += p;
                P[srow * PLDH + sq * 16 + k] = __float2half_rn(p);
            }
            sum += __shfl_xor_sync(0xffffffffu, sum, 1);
            sum += __shfl_xor_sync(0xffffffffu, sum, 2);
            if (sq == 0) {
                float alpha = __expf(m_old - mx);
                mrow[srow] = mx;
                lrow[srow] = lrow[srow] * alpha + sum;
                arow[srow] = alpha;
            }
        }
        __syncthreads();

        #pragma unroll
        for (int f = 0; f < 4; ++f)
            #pragma unroll
            for (int e = 0; e < 8; ++e)
                of[f].x[e] *= arow[wm * 16 + rowid[e]];

        #pragma unroll
        for (int ks = 0; ks < 4; ++ks) {
            wmma::fragment<wmma::matrix_a, 16, 16, 16, __half, wmma::row_major> pa;
            wmma::load_matrix_sync(pa, P + (wm * 16) * PLDH + ks * 16, PLDH);
            #pragma unroll
            for (int jj = 0; jj < 4; ++jj) {
                wmma::fragment<wmma::matrix_b, 16, 16, 16, __half, wmma::row_major> vb;
                wmma::load_matrix_sync(vb, Vs + (ks * 16) * QLDH + wn * 64 + jj * 16, QLDH);
                wmma::mma_sync(of[jj], pa, vb, of[jj]);
            }
        }
        __syncthreads();
    }

    float* Os = (float*)(smg + OFF_K);   // 64 x 132 fp32 staging
    #pragma unroll
    for (int jj = 0; jj < 4; ++jj)
        wmma::store_matrix_sync(Os + (wm * 16) * 132 + wn * 64 + jj * 16,
                                of[jj], 132, wmma::mem_row_major);
    __syncthreads();
    #pragma unroll
    for (int i = 0; i < 8; ++i) {
        int idx = tid + i * 256;
        int r = idx >> 5, c4 = idx & 31;
        float linv = 1.0f / lrow[r];
        float4 v = *(float4*)(Os + r * 132 + c4 * 4);
        __half2 p0 = __floats2half2_rn(v.x * linv, v.y * linv);
        __half2 p1 = __floats2half2_rn(v.z * linv, v.w * linv);
        uint2 u;
        u.x = *(uint32_t*)&p0;
        u.y = *(uint32_t*)&p1;
        *(uint2*)(out + (size_t)(qt * 64 + r) * DMODEL + h * HDIM + c4 * 4) = u;
    }
}

// ================= LayerNorm: one block per row, optional half copy =========
__global__ void __launch_bounds__(256)
ln_kernel(const float* __restrict__ in, const float* __restrict__ g,
          const float* __restrict__ b, float* __restrict__ out,
          __half* __restrict__ out_h)
{
    const int row = blockIdx.x;
    const int tid = threadIdx.x;
    const float4* x4 = (const float4*)(in + (size_t)row * DMODEL);

    float4 v0 = x4[tid];
    float4 v1 = x4[tid + 256];
    float s = v0.x + v0.y + v0.z + v0.w + v1.x + v1.y + v1.z + v1.w;
    float q = v0.x * v0.x + v0.y * v0.y + v0.z * v0.z + v0.w * v0.w
            + v1.x * v1.x + v1.y * v1.y + v1.z * v1.z + v1.w * v1.w;

    #pragma unroll
    for (int o = 16; o > 0; o >>= 1) {
        s += __shfl_down_sync(0xffffffffu, s, o);
        q += __shfl_down_sync(0xffffffffu, q, o);
    }
    __shared__ float rs[8], rq[8], fin[2];
    if ((tid & 31) == 0) { rs[tid >> 5] = s; rq[tid >> 5] = q; }
    __syncthreads();
    if (tid == 0) {
        float S = 0.0f, Q = 0.0f;
        #pragma unroll
        for (int i = 0; i < 8; ++i) { S += rs[i]; Q += rq[i]; }
        float mu  = S * (1.0f / DMODEL);
        float var = Q * (1.0f / DMODEL) - mu * mu;
        fin[0] = mu;
        fin[1] = rsqrtf(var + LN_EPS);
    }
    __syncthreads();
    float mu = fin[0], r = fin[1];

    float4 g0 = ((const float4*)g)[tid], g1 = ((const float4*)g)[tid + 256];
    float4 b0 = ((const float4*)b)[tid], b1 = ((const float4*)b)[tid + 256];
    float4 o0, o1;
    o0.x = (v0.x - mu) * r * g0.x + b0.x;
    o0.y = (v0.y - mu) * r * g0.y + b0.y;
    o0.z = (v0.z - mu) * r * g0.z + b0.z;
    o0.w = (v0.w - mu) * r * g0.w + b0.w;
    o1.x = (v1.x - mu) * r * g1.x + b1.x;
    o1.y = (v1.y - mu) * r * g1.y + b1.y;
    o1.z = (v1.z - mu) * r * g1.z + b1.z;
    o1.w = (v1.w - mu) * r * g1.w + b1.w;
    ((float4*)(out + (size_t)row * DMODEL))[tid]       = o0;
    ((float4*)(out + (size_t)row * DMODEL))[tid + 256] = o1;
    if (out_h) {
        __half2 a0 = __floats2half2_rn(o0.x, o0.y);
        __half2 a1 = __floats2half2_rn(o0.z, o0.w);
        __half2 a2 = __floats2half2_rn(o1.x, o1.y);
        __half2 a3 = __floats2half2_rn(o1.z, o1.w);
        uint2 u0, u1;
        u0.x = *(uint32_t*)&a0; u0.y = *(uint32_t*)&a1;
        u1.x = *(uint32_t*)&a2; u1.y = *(uint32_t*)&a3;
        ((uint2*)(out_h + (size_t)row * DMODEL))[tid]       = u0;
        ((uint2*)(out_h + (size_t)row * DMODEL))[tid + 256] = u1;
    }
}

// ================= launch ===================================================
extern "C" void kernel_launch(void* const* d_in, const int* in_sizes, int n_in,
                              void* d_out, int out_size)
{
    (void)in_sizes; (void)n_in; (void)out_size;

    const float* x     = (const float*)d_in[0];
    const float* C_w   = (const float*)d_in[1];
    const float* C_b   = (const float*)d_in[2];
    const float* lin_w = (const float*)d_in[3];
    const float* lin_b = (const float*)d_in[4];
    const float* ff1_w = (const float*)d_in[5];
    const float* ff1_b = (const float*)d_in[6];
    const float* ff2_w = (const float*)d_in[7];
    const float* ff2_b = (const float*)d_in[8];
    const float* ln1_g = (const float*)d_in[9];
    const float* ln1_b = (const float*)d_in[10];
    const float* ln2_g = (const float*)d_in[11];
    const float* ln2_b = (const float*)d_in[12];
    float* out = (float*)d_out;

    __half *c, *attn, *h1h, *ff, *xh, *Cwh, *linh, *ff1h, *ff2h;
    float *res1, *h1, *res2;
    cudaGetSymbolAddress((void**)&c,    g_c);
    cudaGetSymbolAddress((void**)&attn, g_attn);
    cudaGetSymbolAddress((void**)&res1, g_res1);
    cudaGetSymbolAddress((void**)&h1,   g_h1);
    cudaGetSymbolAddress((void**)&h1h,  g_h1h);
    cudaGetSymbolAddress((void**)&ff,   g_ff);
    cudaGetSymbolAddress((void**)&res2, g_res2);
    cudaGetSymbolAddress((void**)&xh,   g_xh);
    cudaGetSymbolAddress((void**)&Cwh,  g_Cwh);
    cudaGetSymbolAddress((void**)&linh, g_linh);
    cudaGetSymbolAddress((void**)&ff1h, g_ff1h);
    cudaGetSymbolAddress((void**)&ff2h, g_ff2h);

    cudaFuncSetAttribute((const void*)gemm_fp16<EPI_BIAS, true>,       cudaFuncAttributeMaxDynamicSharedMemorySize, GEMM_SMEM);
    cudaFuncSetAttribute((const void*)gemm_fp16<EPI_BIAS_RES, false>,  cudaFuncAttributeMaxDynamicSharedMemorySize, GEMM_SMEM);
    cudaFuncSetAttribute((const void*)gemm_fp16<EPI_BIAS_GELU, true>,  cudaFuncAttributeMaxDynamicSharedMemorySize, GEMM_SMEM);
    cudaFuncSetAttribute((const void*)attn_kernel,                     cudaFuncAttributeMaxDynamicSharedMemorySize, ATT_SMEM);

    // 0) convert inputs to half
    f2h_kernel<<<512, 256>>>(x,     xh,   SEQ * DMODEL / 4);
    f2h_kernel<<<512, 256>>>(C_w,   Cwh,  DMODEL * 3 * DMODEL / 4);
    f2h_kernel<<<512, 256>>>(lin_w, linh, DMODEL * DMODEL / 4);
    f2h_kernel<<<512, 256>>>(ff1_w, ff1h, DMODEL * INNER / 4);
    f2h_kernel<<<512, 256>>>(ff2_w, ff2h, INNER * DMODEL / 4);

    // 1) QKV: c = half(xh @ C_w + C_b)   [2048, 6144]
    gemm_fp16<EPI_BIAS, true><<<dim3(3 * DMODEL / 256, SEQ / 128), 256, GEMM_SMEM>>>(
        xh, Cwh, C_b, nullptr, c, SEQ, 3 * DMODEL, DMODEL);

    // 2) causal attention -> attn (half)
    attn_kernel<<<dim3(SEQ / 64, HEADS), 256, ATT_SMEM>>>(c, attn);

    // 3) res1 = x + attn @ lin_w + lin_b  (fp32)
    gemm_fp16<EPI_BIAS_RES, false><<<dim3(DMODEL / 256, SEQ / 128), 256, GEMM_SMEM>>>(
        attn, linh, lin_b, x, res1, SEQ, DMODEL, DMODEL);

    // 4) h1 = LN1(res1); h1h = half(h1)
    ln_kernel<<<SEQ, 256>>>(res1, ln1_g, ln1_b, h1, h1h);

    // 5) ff = half(gelu(h1h @ ff1_w + ff1_b))   [2048, 8192]
    gemm_fp16<EPI_BIAS_GELU, true><<<dim3(INNER / 256, SEQ / 128), 256, GEMM_SMEM>>>(
        h1h, ff1h, ff1_b, nullptr, ff, SEQ, INNER, DMODEL);

    // 6) res2 = h1 + ff @ ff2_w + ff2_b  (fp32)
    gemm_fp16<EPI_BIAS_RES, false><<<dim3(DMODEL / 256, SEQ / 128), 256, GEMM_SMEM>>>(
        ff, ff2h, ff2_b, h1, res2, SEQ, DMODEL, INNER);

    // 7) out = LN2(res2)
    ln_kernel<<<SEQ, 256>>>(res2, ln2_g, ln2_b, out, nullptr);
}

// round 8
// speedup vs baseline: 1.0351x; 1.0351x over previous
#include <cuda_runtime.h>
#include <cuda_fp16.h>
#include <cstdint>
#include <mma.h>
#include <math.h>

using namespace nvcuda;

// ---------------- constants ----------------
#define SEQ      2048
#define DMODEL   2048
#define HEADS    16
#define HDIM     128
#define INNER    8192
#define LN_EPS   1e-5f

// ---------------- scratch (static device memory; no allocations) ----------
__device__ __half g_c[SEQ * 3 * DMODEL];     // QKV (half)
__device__ __half g_attn[SEQ * DMODEL];      // attention out (half)
__device__ float  g_res1[SEQ * DMODEL];      // x + proj(attn)
__device__ float  g_h1[SEQ * DMODEL];        // LN1 out fp32 (residual)
__device__ __half g_h1h[SEQ * DMODEL];       // LN1 out half (GEMM A)
__device__ __half g_ff[SEQ * INNER];         // gelu(...) half
__device__ float  g_res2[SEQ * DMODEL];
__device__ __half g_xh[SEQ * DMODEL];        // x half
__device__ __half g_Cwh[DMODEL * 3 * DMODEL];
__device__ __half g_linh[DMODEL * DMODEL];
__device__ __half g_ff1h[DMODEL * INNER];
__device__ __half g_ff2h[INNER * DMODEL];

// ---------------- helpers ----------------
__device__ __forceinline__ float gelu_f(float v) {
    return 0.5f * v * (1.0f + erff(v * 0.7071067811865476f));
}
__device__ __forceinline__ uint32_t smem_u32(const void* p) {
    uint32_t a;
    asm("{ .reg .u64 t; cvta.to.shared.u64 t, %1; cvt.u32.u64 %0, t; }"
        : "=r"(a) : "l"(p));
    return a;
}
__device__ __forceinline__ void cp16(uint32_t dst, const void* src) {
    asm volatile("cp.async.cg.shared.global [%0], [%1], 16;" :: "r"(dst), "l"(src));
}
#define CP_COMMIT() asm volatile("cp.async.commit_group;" ::: "memory")
#define CP_WAIT(n)  asm volatile("cp.async.wait_group %0;" :: "n"(n) : "memory")

// ================= float -> half conversion =================================
__global__ void __launch_bounds__(256)
f2h_kernel(const float* __restrict__ in, __half* __restrict__ out, int n4)
{
    int i = blockIdx.x * 256 + threadIdx.x;
    int stride = gridDim.x * 256;
    for (; i < n4; i += stride) {
        float4 v = ((const float4*)in)[i];
        __half2 p0 = __floats2half2_rn(v.x, v.y);
        __half2 p1 = __floats2half2_rn(v.z, v.w);
        uint2 u;
        u.x = *(uint32_t*)&p0;
        u.y = *(uint32_t*)&p1;
        ((uint2*)out)[i] = u;
    }
}

// ================= FP16 WMMA GEMM (round-6 config: 128x128x64, 2 CTA/SM) ====
#define ALD 72     // halves; 144B/row
#define BLD 136    // halves; 272B/row
#define GSTAGES 3
#define STAGE_BYTES (128 * 144 + 64 * 272)      // 35840
#define GEMM_SMEM   (GSTAGES * STAGE_BYTES)     // 107520

enum { EPI_BIAS = 0, EPI_BIAS_RES = 1, EPI_BIAS_GELU = 2 };

template <int EPI, bool OUTH>
__global__ void __launch_bounds__(256, 2)
gemm_fp16(const __half* __restrict__ A, const __half* __restrict__ B,
          const float* __restrict__ bias, const float* __restrict__ res,
          void* __restrict__ Cout, int M, int N, int K)
{
    extern __shared__ char smg[];
    const uint32_t sbase = smem_u32(smg);

    const int tid  = threadIdx.x;
    const int bm   = blockIdx.y;
    const int bn   = blockIdx.x;
    const int warp = tid >> 5;
    const int wm   = warp & 3;
    const int wn   = warp >> 2;

    wmma::fragment<wmma::accumulator, 16, 16, 16, float> cf[2][4];
    #pragma unroll
    for (int i = 0; i < 2; ++i)
        #pragma unroll
        for (int j = 0; j < 4; ++j)
            wmma::fill_fragment(cf[i][j], 0.0f);

    const __half* Aptr = A + (size_t)(bm * 128) * K;
    const __half* Bptr = B + (size_t)bn * 128;
    const int nT = K >> 6;

    auto load_stage = [&](int s, int kt) {
        uint32_t sa = sbase + s * STAGE_BYTES;
        uint32_t sb = sa + 128 * 144;
        #pragma unroll
        for (int i = 0; i < 4; ++i) {
            int idx = tid + i * 256;
            int r = idx >> 3, c = idx & 7;
            cp16(sa + r * 144 + c * 16, Aptr + (size_t)r * K + kt * 64 + c * 8);
        }
        #pragma unroll
        for (int i = 0; i < 4; ++i) {
            int idx = tid + i * 256;
            int r = idx >> 4, c = idx & 15;
            cp16(sb + r * 272 + c * 16, Bptr + (size_t)(kt * 64 + r) * N + c * 8);
        }
    };

    load_stage(0, 0); CP_COMMIT();
    load_stage(1, 1); CP_COMMIT();

    for (int kt = 0; kt < nT; ++kt) {
        const int s = kt % GSTAGES;
        if (kt + 2 < nT) { load_stage((kt + 2) % GSTAGES, kt + 2); CP_COMMIT(); CP_WAIT(2); }
        else if (kt + 1 < nT) { CP_WAIT(1); }
        else { CP_WAIT(0); }
        __syncthreads();

        const __half* As = (const __half*)(smg + s * STAGE_BYTES);
        const __half* Bs = As + 128 * ALD;
        #pragma unroll
        for (int ks = 0; ks < 4; ++ks) {
            wmma::fragment<wmma::matrix_a, 16, 16, 16, __half, wmma::row_major> af[2];
            wmma::fragment<wmma::matrix_b, 16, 16, 16, __half, wmma::row_major> bf[4];
            #pragma unroll
            for (int i = 0; i < 2; ++i)
                wmma::load_matrix_sync(af[i], As + (wm * 32 + i * 16) * ALD + ks * 16, ALD);
            #pragma unroll
            for (int j = 0; j < 4; ++j)
                wmma::load_matrix_sync(bf[j], Bs + (ks * 16) * BLD + wn * 64 + j * 16, BLD);
            #pragma unroll
            for (int i = 0; i < 2; ++i)
                #pragma unroll
                for (int j = 0; j < 4; ++j)
                    wmma::mma_sync(cf[i][j], af[i], bf[j], cf[i][j]);
        }
        __syncthreads();
    }

    float* Cs = (float*)smg;  // 128x128 fp32 staging
    #pragma unroll
    for (int i = 0; i < 2; ++i)
        #pragma unroll
        for (int j = 0; j < 4; ++j)
            wmma::store_matrix_sync(Cs + (wm * 32 + i * 16) * 128 + wn * 64 + j * 16,
                                    cf[i][j], 128, wmma::mem_row_major);
    __syncthreads();

    #pragma unroll
    for (int it = 0; it < 16; ++it) {
        int f4 = tid + it * 256;
        int r = f4 >> 5, c4 = f4 & 31;
        float4 v = ((float4*)Cs)[f4];
        int gn = bn * 128 + c4 * 4;
        float4 bv = *(const float4*)(bias + gn);
        v.x += bv.x; v.y += bv.y; v.z += bv.z; v.w += bv.w;
        size_t goff = (size_t)(bm * 128 + r) * N + gn;
        if (EPI == EPI_BIAS_RES) {
            float4 rv = *(const float4*)(res + goff);
            v.x += rv.x; v.y += rv.y; v.z += rv.z; v.w += rv.w;
        }
        if (EPI == EPI_BIAS_GELU) {
            v.x = gelu_f(v.x); v.y = gelu_f(v.y);
            v.z = gelu_f(v.z); v.w = gelu_f(v.w);
        }
        if (OUTH) {
            __half2 p0 = __floats2half2_rn(v.x, v.y);
            __half2 p1 = __floats2half2_rn(v.z, v.w);
            uint2 u;
            u.x = *(uint32_t*)&p0;
            u.y = *(uint32_t*)&p1;
            *(uint2*)((__half*)Cout + goff) = u;
        } else {
            *(float4*)((float*)Cout + goff) = v;
        }
    }
}

// ================= causal flash attention, BQ=128, BK=64 ====================
// c half [SEQ, 3*DMODEL]. Block (qt, h), 256 thr = 8 warps.
// Each warp owns a 16-row Q strip; S tile 128x64; O tile 128x128.
#define QLDH 136                              // halves (272B rows)
#define SLDF 68                               // fp32
#define PLDH 72                               // halves
#define OFF_Q   0                             // 128*272 = 34816 B
#define OFF_K   34816                         // 2 x 17408
#define OFF_V   (OFF_K + 2 * 17408)           // 2 x 17408
#define OFF_S   (OFF_V + 2 * 17408)           // 128*68*4 = 34816 B
#define OFF_P   (OFF_S + 34816)               // 128*72*2 = 18432 B
#define OFF_RP  (OFF_P + 18432)               // 256*4
#define OFF_M   (OFF_RP + 1024)               // 128*4
#define OFF_L   (OFF_M + 512)
#define OFF_A   (OFF_L + 512)
#define ATT_SMEM (OFF_A + 512)

__global__ void __launch_bounds__(256)
attn_kernel(const __half* __restrict__ c, __half* __restrict__ out)
{
    const int h  = blockIdx.y;
    const int qt = gridDim.x - 1 - blockIdx.x;   // heavy tiles first

    extern __shared__ char smg[];
    const uint32_t sbase = smem_u32(smg);
    __half* Qs    = (__half*)(smg + OFF_Q);
    float*  S     = (float*)(smg + OFF_S);
    __half* P     = (__half*)(smg + OFF_P);
    float* rowpat = (float*)(smg + OFF_RP);
    float* mrow   = (float*)(smg + OFF_M);
    float* lrow   = (float*)(smg + OFF_L);
    float* arow   = (float*)(smg + OFF_A);

    const int tid  = threadIdx.x;
    const int wm   = tid >> 5;                 // warp = 16-row strip

    auto load_kv = [&](int buf, int j) {
        uint32_t kb = sbase + OFF_K + buf * 17408;
        uint32_t vb = sbase + OFF_V + buf * 17408;
        const __half* base = c + (size_t)(j * 64) * (3 * DMODEL) + h * HDIM;
        #pragma unroll
        for (int i = 0; i < 4; ++i) {
            int idx = tid + i * 256;
            int r = idx >> 4, cc = idx & 15;
            const __half* rp = base + (size_t)r * (3 * DMODEL) + cc * 8;
            cp16(kb + r * 272 + cc * 16, rp + DMODEL);
            cp16(vb + r * 272 + cc * 16, rp + 2 * DMODEL);
        }
    };

    load_kv(0, 0); CP_COMMIT();

    // Q tile: 128 rows x 128 halves (2048 chunks, 8/thread)
    #pragma unroll
    for (int i = 0; i < 8; ++i) {
        int idx = tid + i * 256;
        int r = idx >> 4, cc = idx & 15;
        *(uint4*)((char*)Qs + r * 272 + cc * 16) =
            *(const uint4*)(c + (size_t)(qt * 128 + r) * (3 * DMODEL) + h * HDIM + cc * 8);
    }
    rowpat[tid] = (float)(tid >> 4);
    if (tid < 128) { mrow[tid] = -1e30f; lrow[tid] = 0.0f; }
    __syncthreads();

    wmma::fragment<wmma::accumulator, 16, 16, 16, float> rowf;
    wmma::load_matrix_sync(rowf, rowpat, 16, wmma::mem_row_major);
    int rowid[8];
    #pragma unroll
    for (int e = 0; e < 8; ++e) rowid[e] = (int)rowf.x[e];

    wmma::fragment<wmma::accumulator, 16, 16, 16, float> of[8];
    #pragma unroll
    for (int j = 0; j < 8; ++j) wmma::fill_fragment(of[j], 0.0f);

    const float scale = 0.022097086912079608f;  // 1/sqrt(2048)
    const int srow = tid >> 1, sq = tid & 1;    // 2 threads per row, 32 cols each
    const int nkv = 2 * qt + 2;                 // KV tiles of 64 covering causal span

    for (int j = 0; j < nkv; ++j) {
        if (j + 1 < nkv) { load_kv((j + 1) & 1, j + 1); CP_COMMIT(); CP_WAIT(1); }
        else             { CP_WAIT(0); }
        __syncthreads();

        const __half* Ks = (const __half*)(smg + OFF_K + (j & 1) * 17408);
        const __half* Vs = (const __half*)(smg + OFF_V + (j & 1) * 17408);

        // S[128x64] = Q @ K^T : warp wm computes rows [wm*16, wm*16+16)
        {
            wmma::fragment<wmma::accumulator, 16, 16, 16, float> sf[4];
            #pragma unroll
            for (int jj = 0; jj < 4; ++jj) wmma::fill_fragment(sf[jj], 0.0f);
            #pragma unroll
            for (int ks = 0; ks < 8; ++ks) {
                wmma::fragment<wmma::matrix_a, 16, 16, 16, __half, wmma::row_major> af;
                wmma::load_matrix_sync(af, Qs + (wm * 16) * QLDH + ks * 16, QLDH);
                #pragma unroll
                for (int jj = 0; jj < 4; ++jj) {
                    wmma::fragment<wmma::matrix_b, 16, 16, 16, __half, wmma::col_major> bf;
                    wmma::load_matrix_sync(bf, Ks + (jj * 16) * QLDH + ks * 16, QLDH);
                    wmma::mma_sync(sf[jj], af, bf, sf[jj]);
                }
            }
            #pragma unroll
            for (int jj = 0; jj < 4; ++jj)
                wmma::store_matrix_sync(S + (wm * 16) * SLDF + jj * 16,
                                        sf[jj], SLDF, wmma::mem_row_major);
        }
        __syncthreads();

        // online softmax: 2 threads/row, 32 cols each, pair shuffle
        {
            const int qglob = qt * 128 + srow;
            const int kbase = j * 64;
            float m_old = mrow[srow];
            float mx = m_old;
            float sv[32];
            #pragma unroll
            for (int k = 0; k < 32; ++k) {
                int kcol = sq * 32 + k;
                float v = S[srow * SLDF + kcol] * scale;
                if (kbase + kcol > qglob) v = -1e30f;
                sv[k] = v;
                mx = fmaxf(mx, v);
            }
            mx = fmaxf(mx, __shfl_xor_sync(0xffffffffu, mx, 1));
            float sum = 0.0f;
            #pragma unroll
            for (int k = 0; k < 32; ++k) {
                float p = __expf(sv[k] - mx);
                sum += p;
                P[srow * PLDH + sq * 32 + k] = __float2half_rn(p);
            }
            sum += __shfl_xor_sync(0xffffffffu, sum, 1);
            if (sq == 0) {
                float alpha = __expf(m_old - mx);
                mrow[srow] = mx;
                lrow[srow] = lrow[srow] * alpha + sum;
                arow[srow] = alpha;
            }
        }
        __syncthreads();

        // rescale O, then O[128x128] += P @ V (warp: 16 rows x 128 cols)
        #pragma unroll
        for (int f = 0; f < 8; ++f)
            #pragma unroll
            for (int e = 0; e < 8; ++e)
                of[f].x[e] *= arow[wm * 16 + rowid[e]];

        #pragma unroll
        for (int ks = 0; ks < 4; ++ks) {
            wmma::fragment<wmma::matrix_a, 16, 16, 16, __half, wmma::row_major> pa;
            wmma::load_matrix_sync(pa, P + (wm * 16) * PLDH + ks * 16, PLDH);
            #pragma unroll
            for (int jj = 0; jj < 8; ++jj) {
                wmma::fragment<wmma::matrix_b, 16, 16, 16, __half, wmma::row_major> vb;
                wmma::load_matrix_sync(vb, Vs + (ks * 16) * QLDH + jj * 16, QLDH);
                wmma::mma_sync(of[jj], pa, vb, of[jj]);
            }
        }
        __syncthreads();
    }

    // O staging: 128 x 132 fp32 in K/V region (67584 B <= 69632 B)
    float* Os = (float*)(smg + OFF_K);
    #pragma unroll
    for (int jj = 0; jj < 8; ++jj)
        wmma::store_matrix_sync(Os + (wm * 16) * 132 + jj * 16,
                                of[jj], 132, wmma::mem_row_major);
    __syncthreads();
    #pragma unroll
    for (int i = 0; i < 16; ++i) {
        int idx = tid + i * 256;             // 4096 float4
        int r = idx >> 5, c4 = idx & 31;
        float linv = 1.0f / lrow[r];
        float4 v = *(float4*)(Os + r * 132 + c4 * 4);
        __half2 p0 = __floats2half2_rn(v.x * linv, v.y * linv);
        __half2 p1 = __floats2half2_rn(v.z * linv, v.w * linv);
        uint2 u;
        u.x = *(uint32_t*)&p0;
        u.y = *(uint32_t*)&p1;
        *(uint2*)(out + (size_t)(qt * 128 + r) * DMODEL + h * HDIM + c4 * 4) = u;
    }
}

// ================= LayerNorm: one block per row, optional half copy =========
__global__ void __launch_bounds__(256)
ln_kernel(const float* __restrict__ in, const float* __restrict__ g,
          const float* __restrict__ b, float* __restrict__ out,
          __half* __restrict__ out_h)
{
    const int row = blockIdx.x;
    const int tid = threadIdx.x;
    const float4* x4 = (const float4*)(in + (size_t)row * DMODEL);

    float4 v0 = x4[tid];
    float4 v1 = x4[tid + 256];
    float s = v0.x + v0.y + v0.z + v0.w + v1.x + v1.y + v1.z + v1.w;
    float q = v0.x * v0.x + v0.y * v0.y + v0.z * v0.z + v0.w * v0.w
            + v1.x * v1.x + v1.y * v1.y + v1.z * v1.z + v1.w * v1.w;

    #pragma unroll
    for (int o = 16; o > 0; o >>= 1) {
        s += __shfl_down_sync(0xffffffffu, s, o);
        q += __shfl_down_sync(0xffffffffu, q, o);
    }
    __shared__ float rs[8], rq[8], fin[2];
    if ((tid & 31) == 0) { rs[tid >> 5] = s; rq[tid >> 5] = q; }
    __syncthreads();
    if (tid == 0) {
        float S = 0.0f, Q = 0.0f;
        #pragma unroll
        for (int i = 0; i < 8; ++i) { S += rs[i]; Q += rq[i]; }
        float mu  = S * (1.0f / DMODEL);
        float var = Q * (1.0f / DMODEL) - mu * mu;
        fin[0] = mu;
        fin[1] = rsqrtf(var + LN_EPS);
    }
    __syncthreads();
    float mu = fin[0], r = fin[1];

    float4 g0 = ((const float4*)g)[tid], g1 = ((const float4*)g)[tid + 256];
    float4 b0 = ((const float4*)b)[tid], b1 = ((const float4*)b)[tid + 256];
    float4 o0, o1;
    o0.x = (v0.x - mu) * r * g0.x + b0.x;
    o0.y = (v0.y - mu) * r * g0.y + b0.y;
    o0.z = (v0.z - mu) * r * g0.z + b0.z;
    o0.w = (v0.w - mu) * r * g0.w + b0.w;
    o1.x = (v1.x - mu) * r * g1.x + b1.x;
    o1.y = (v1.y - mu) * r * g1.y + b1.y;
    o1.z = (v1.z - mu) * r * g1.z + b1.z;
    o1.w = (v1.w - mu) * r * g1.w + b1.w;
    ((float4*)(out + (size_t)row * DMODEL))[tid]       = o0;
    ((float4*)(out + (size_t)row * DMODEL))[tid + 256] = o1;
    if (out_h) {
        __half2 a0 = __floats2half2_rn(o0.x, o0.y);
        __half2 a1 = __floats2half2_rn(o0.z, o0.w);
        __half2 a2 = __floats2half2_rn(o1.x, o1.y);
        __half2 a3 = __floats2half2_rn(o1.z, o1.w);
        uint2 u0, u1;
        u0.x = *(uint32_t*)&a0; u0.y = *(uint32_t*)&a1;
        u1.x = *(uint32_t*)&a2; u1.y = *(uint32_t*)&a3;
        ((uint2*)(out_h + (size_t)row * DMODEL))[tid]       = u0;
        ((uint2*)(out_h + (size_t)row * DMODEL))[tid + 256] = u1;
    }
}

// ================= launch ===================================================
extern "C" void kernel_launch(void* const* d_in, const int* in_sizes, int n_in,
                              void* d_out, int out_size)
{
    (void)in_sizes; (void)n_in; (void)out_size;

    const float* x     = (const float*)d_in[0];
    const float* C_w   = (const float*)d_in[1];
    const float* C_b   = (const float*)d_in[2];
    const float* lin_w = (const float*)d_in[3];
    const float* lin_b = (const float*)d_in[4];
    const float* ff1_w = (const float*)d_in[5];
    const float* ff1_b = (const float*)d_in[6];
    const float* ff2_w = (const float*)d_in[7];
    const float* ff2_b = (const float*)d_in[8];
    const float* ln1_g = (const float*)d_in[9];
    const float* ln1_b = (const float*)d_in[10];
    const float* ln2_g = (const float*)d_in[11];
    const float* ln2_b = (const float*)d_in[12];
    float* out = (float*)d_out;

    __half *c, *attn, *h1h, *ff, *xh, *Cwh, *linh, *ff1h, *ff2h;
    float *res1, *h1, *res2;
    cudaGetSymbolAddress((void**)&c,    g_c);
    cudaGetSymbolAddress((void**)&attn, g_attn);
    cudaGetSymbolAddress((void**)&res1, g_res1);
    cudaGetSymbolAddress((void**)&h1,   g_h1);
    cudaGetSymbolAddress((void**)&h1h,  g_h1h);
    cudaGetSymbolAddress((void**)&ff,   g_ff);
    cudaGetSymbolAddress((void**)&res2, g_res2);
    cudaGetSymbolAddress((void**)&xh,   g_xh);
    cudaGetSymbolAddress((void**)&Cwh,  g_Cwh);
    cudaGetSymbolAddress((void**)&linh, g_linh);
    cudaGetSymbolAddress((void**)&ff1h, g_ff1h);
    cudaGetSymbolAddress((void**)&ff2h, g_ff2h);

    cudaFuncSetAttribute((const void*)gemm_fp16<EPI_BIAS, true>,       cudaFuncAttributeMaxDynamicSharedMemorySize, GEMM_SMEM);
    cudaFuncSetAttribute((const void*)gemm_fp16<EPI_BIAS_RES, false>,  cudaFuncAttributeMaxDynamicSharedMemorySize, GEMM_SMEM);
    cudaFuncSetAttribute((const void*)gemm_fp16<EPI_BIAS_GELU, true>,  cudaFuncAttributeMaxDynamicSharedMemorySize, GEMM_SMEM);
    cudaFuncSetAttribute((const void*)attn_kernel,                     cudaFuncAttributeMaxDynamicSharedMemorySize, ATT_SMEM);

    // 0) convert inputs to half
    f2h_kernel<<<512, 256>>>(x,     xh,   SEQ * DMODEL / 4);
    f2h_kernel<<<512, 256>>>(C_w,   Cwh,  DMODEL * 3 * DMODEL / 4);
    f2h_kernel<<<512, 256>>>(lin_w, linh, DMODEL * DMODEL / 4);
    f2h_kernel<<<512, 256>>>(ff1_w, ff1h, DMODEL * INNER / 4);
    f2h_kernel<<<512, 256>>>(ff2_w, ff2h, INNER * DMODEL / 4);

    // 1) QKV: c = half(xh @ C_w + C_b)   [2048, 6144]
    gemm_fp16<EPI_BIAS, true><<<dim3(3 * DMODEL / 128, SEQ / 128), 256, GEMM_SMEM>>>(
        xh, Cwh, C_b, nullptr, c, SEQ, 3 * DMODEL, DMODEL);

    // 2) causal attention -> attn (half), BQ=128
    attn_kernel<<<dim3(SEQ / 128, HEADS), 256, ATT_SMEM>>>(c, attn);

    // 3) res1 = x + attn @ lin_w + lin_b  (fp32)
    gemm_fp16<EPI_BIAS_RES, false><<<dim3(DMODEL / 128, SEQ / 128), 256, GEMM_SMEM>>>(
        attn, linh, lin_b, x, res1, SEQ, DMODEL, DMODEL);

    // 4) h1 = LN1(res1); h1h = half(h1)
    ln_kernel<<<SEQ, 256>>>(res1, ln1_g, ln1_b, h1, h1h);

    // 5) ff = half(gelu(h1h @ ff1_w + ff1_b))   [2048, 8192]
    gemm_fp16<EPI_BIAS_GELU, true><<<dim3(INNER / 128, SEQ / 128), 256, GEMM_SMEM>>>(
        h1h, ff1h, ff1_b, nullptr, ff, SEQ, INNER, DMODEL);

    // 6) res2 = h1 + ff @ ff2_w + ff2_b  (fp32)
    gemm_fp16<EPI_BIAS_RES, false><<<dim3(DMODEL / 128, SEQ / 128), 256, GEMM_SMEM>>>(
        ff, ff2h, ff2_b, h1, res2, SEQ, DMODEL, INNER);

    // 7) out = LN2(res2)
    ln_kernel<<<SEQ, 256>>>(res2, ln2_g, ln2_b, out, nullptr);
}

// round 9
// speedup vs baseline: 1.0962x; 1.0590x over previous
#include <cuda_runtime.h>
#include <cuda_fp16.h>
#include <cstdint>
#include <mma.h>
#include <math.h>

using namespace nvcuda;

// ---------------- constants ----------------
#define SEQ      2048
#define DMODEL   2048
#define HEADS    16
#define HDIM     128
#define INNER    8192
#define LN_EPS   1e-5f

// ---------------- scratch (static device memory; no allocations) ----------
__device__ __half g_c[SEQ * 3 * DMODEL];     // QKV (half)
__device__ __half g_attn[SEQ * DMODEL];      // attention out (half)
__device__ float  g_res1[SEQ * DMODEL];      // x + proj(attn)
__device__ float  g_h1[SEQ * DMODEL];        // LN1 out fp32 (residual)
__device__ __half g_h1h[SEQ * DMODEL];       // LN1 out half (GEMM A)
__device__ __half g_ff[SEQ * INNER];         // gelu(...) half
__device__ float  g_res2[SEQ * DMODEL];
__device__ __half g_xh[SEQ * DMODEL];        // x half
__device__ __half g_Cwh[DMODEL * 3 * DMODEL];
__device__ __half g_linh[DMODEL * DMODEL];
__device__ __half g_ff1h[DMODEL * INNER];
__device__ __half g_ff2h[INNER * DMODEL];

// ---------------- helpers ----------------
__device__ __forceinline__ float gelu_f(float v) {
    return 0.5f * v * (1.0f + erff(v * 0.7071067811865476f));
}
__device__ __forceinline__ uint32_t smem_u32(const void* p) {
    uint32_t a;
    asm("{ .reg .u64 t; cvta.to.shared.u64 t, %1; cvt.u32.u64 %0, t; }"
        : "=r"(a) : "l"(p));
    return a;
}
__device__ __forceinline__ void cp16(uint32_t dst, const void* src) {
    asm volatile("cp.async.cg.shared.global [%0], [%1], 16;" :: "r"(dst), "l"(src));
}
#define CP_COMMIT() asm volatile("cp.async.commit_group;" ::: "memory")
#define CP_WAIT(n)  asm volatile("cp.async.wait_group %0;" :: "n"(n) : "memory")

// ================= float -> half conversion =================================
__global__ void __launch_bounds__(256)
f2h_kernel(const float* __restrict__ in, __half* __restrict__ out, int n4)
{
    int i = blockIdx.x * 256 + threadIdx.x;
    int stride = gridDim.x * 256;
    for (; i < n4; i += stride) {
        float4 v = ((const float4*)in)[i];
        __half2 p0 = __floats2half2_rn(v.x, v.y);
        __half2 p1 = __floats2half2_rn(v.z, v.w);
        uint2 u;
        u.x = *(uint32_t*)&p0;
        u.y = *(uint32_t*)&p1;
        ((uint2*)out)[i] = u;
    }
}

// ================= FP16 WMMA GEMM, 128x128x64, 3-stage, 1 barrier/k-tile ====
#define ALD 72     // halves; 144B/row
#define BLD 136    // halves; 272B/row
#define GSTAGES 3
#define STAGE_BYTES (128 * 144 + 64 * 272)      // 35840
#define GEMM_SMEM   (GSTAGES * STAGE_BYTES)     // 107520

enum { EPI_BIAS = 0, EPI_BIAS_RES = 1, EPI_BIAS_GELU = 2 };

template <int EPI, bool OUTH>
__global__ void __launch_bounds__(256, 2)
gemm_fp16(const __half* __restrict__ A, const __half* __restrict__ B,
          const float* __restrict__ bias, const float* __restrict__ res,
          void* __restrict__ Cout, int M, int N, int K)
{
    extern __shared__ char smg[];
    const uint32_t sbase = smem_u32(smg);

    const int tid  = threadIdx.x;
    const int bm   = blockIdx.y;
    const int bn   = blockIdx.x;
    const int warp = tid >> 5;
    const int wm   = warp & 3;
    const int wn   = warp >> 2;

    wmma::fragment<wmma::accumulator, 16, 16, 16, float> cf[2][4];
    #pragma unroll
    for (int i = 0; i < 2; ++i)
        #pragma unroll
        for (int j = 0; j < 4; ++j)
            wmma::fill_fragment(cf[i][j], 0.0f);

    const __half* Aptr = A + (size_t)(bm * 128) * K;
    const __half* Bptr = B + (size_t)bn * 128;
    const int nT = K >> 6;

    auto load_stage = [&](int s, int kt) {
        uint32_t sa = sbase + s * STAGE_BYTES;
        uint32_t sb = sa + 128 * 144;
        #pragma unroll
        for (int i = 0; i < 4; ++i) {
            int idx = tid + i * 256;
            int r = idx >> 3, c = idx & 7;
            cp16(sa + r * 144 + c * 16, Aptr + (size_t)r * K + kt * 64 + c * 8);
        }
        #pragma unroll
        for (int i = 0; i < 4; ++i) {
            int idx = tid + i * 256;
            int r = idx >> 4, c = idx & 15;
            cp16(sb + r * 272 + c * 16, Bptr + (size_t)(kt * 64 + r) * N + c * 8);
        }
    };

    load_stage(0, 0); CP_COMMIT();
    load_stage(1, 1); CP_COMMIT();

    for (int kt = 0; kt < nT; ++kt) {
        if (kt + 1 < nT) { CP_WAIT(1); } else { CP_WAIT(0); }
        __syncthreads();   // stage kt visible to all; all prior MMAs retired

        // prefetch stage kt+2 (overwrites buffer (kt-1)%3 — retired by barrier)
        if (kt + 2 < nT) { load_stage((kt + 2) % GSTAGES, kt + 2); CP_COMMIT(); }

        const __half* As = (const __half*)(smg + (kt % GSTAGES) * STAGE_BYTES);
        const __half* Bs = As + 128 * ALD;
        #pragma unroll
        for (int ks = 0; ks < 4; ++ks) {
            wmma::fragment<wmma::matrix_a, 16, 16, 16, __half, wmma::row_major> af[2];
            wmma::fragment<wmma::matrix_b, 16, 16, 16, __half, wmma::row_major> bf[4];
            #pragma unroll
            for (int i = 0; i < 2; ++i)
                wmma::load_matrix_sync(af[i], As + (wm * 32 + i * 16) * ALD + ks * 16, ALD);
            #pragma unroll
            for (int j = 0; j < 4; ++j)
                wmma::load_matrix_sync(bf[j], Bs + (ks * 16) * BLD + wn * 64 + j * 16, BLD);
            #pragma unroll
            for (int i = 0; i < 2; ++i)
                #pragma unroll
                for (int j = 0; j < 4; ++j)
                    wmma::mma_sync(cf[i][j], af[i], bf[j], cf[i][j]);
        }
    }
    __syncthreads();

    float* Cs = (float*)smg;  // 128x128 fp32 staging
    #pragma unroll
    for (int i = 0; i < 2; ++i)
        #pragma unroll
        for (int j = 0; j < 4; ++j)
            wmma::store_matrix_sync(Cs + (wm * 32 + i * 16) * 128 + wn * 64 + j * 16,
                                    cf[i][j], 128, wmma::mem_row_major);
    __syncthreads();

    #pragma unroll
    for (int it = 0; it < 16; ++it) {
        int f4 = tid + it * 256;
        int r = f4 >> 5, c4 = f4 & 31;
        float4 v = ((float4*)Cs)[f4];
        int gn = bn * 128 + c4 * 4;
        float4 bv = *(const float4*)(bias + gn);
        v.x += bv.x; v.y += bv.y; v.z += bv.z; v.w += bv.w;
        size_t goff = (size_t)(bm * 128 + r) * N + gn;
        if (EPI == EPI_BIAS_RES) {
            float4 rv = *(const float4*)(res + goff);
            v.x += rv.x; v.y += rv.y; v.z += rv.z; v.w += rv.w;
        }
        if (EPI == EPI_BIAS_GELU) {
            v.x = gelu_f(v.x); v.y = gelu_f(v.y);
            v.z = gelu_f(v.z); v.w = gelu_f(v.w);
        }
        if (OUTH) {
            __half2 p0 = __floats2half2_rn(v.x, v.y);
            __half2 p1 = __floats2half2_rn(v.z, v.w);
            uint2 u;
            u.x = *(uint32_t*)&p0;
            u.y = *(uint32_t*)&p1;
            *(uint2*)((__half*)Cout + goff) = u;
        } else {
            *(float4*)((float*)Cout + goff) = v;
        }
    }
}

// ================= causal flash attention, BQ=BK=64, P aliased onto S =======
// smem trimmed to 103.75KB so 2 CTAs co-reside per SM.
#define QLDH 136                              // halves (272B rows)
#define SLDF 68                               // fp32 (272B rows)
#define PLDH 136                              // halves, SAME 272B row stride as S
#define OFF_Q   0                             // 64*272 = 17408 B
#define OFF_K   17408                         // 2 x 17408
#define OFF_V   (OFF_K + 2 * 17408)
#define OFF_S   (OFF_V + 2 * 17408)           // 64*68*4 = 17408 B (P aliases this)
#define OFF_RP  (OFF_S + 17408)               // 256*4
#define OFF_M   (OFF_RP + 1024)               // 64*4
#define OFF_L   (OFF_M + 256)
#define OFF_A   (OFF_L + 256)
#define ATT_SMEM (OFF_A + 256)                // 106240 B

__global__ void __launch_bounds__(256, 2)
attn_kernel(const __half* __restrict__ c, __half* __restrict__ out)
{
    const int h  = blockIdx.y;
    const int qt = gridDim.x - 1 - blockIdx.x;   // heavy tiles first

    extern __shared__ char smg[];
    const uint32_t sbase = smem_u32(smg);
    __half* Qs    = (__half*)(smg + OFF_Q);
    float*  S     = (float*)(smg + OFF_S);
    __half* P     = (__half*)(smg + OFF_S);     // aliased: same rows, 272B stride
    float* rowpat = (float*)(smg + OFF_RP);
    float* mrow   = (float*)(smg + OFF_M);
    float* lrow   = (float*)(smg + OFF_L);
    float* arow   = (float*)(smg + OFF_A);

    const int tid  = threadIdx.x;
    const int warp = tid >> 5;
    const int wm   = warp & 3;
    const int wn   = warp >> 2;

    auto load_kv = [&](int buf, int j) {
        uint32_t kb = sbase + OFF_K + buf * 17408;
        uint32_t vb = sbase + OFF_V + buf * 17408;
        const __half* base = c + (size_t)(j * 64) * (3 * DMODEL) + h * HDIM;
        #pragma unroll
        for (int i = 0; i < 4; ++i) {
            int idx = tid + i * 256;
            int r = idx >> 4, cc = idx & 15;
            const __half* rp = base + (size_t)r * (3 * DMODEL) + cc * 8;
            cp16(kb + r * 272 + cc * 16, rp + DMODEL);
            cp16(vb + r * 272 + cc * 16, rp + 2 * DMODEL);
        }
    };

    load_kv(0, 0); CP_COMMIT();

    #pragma unroll
    for (int i = 0; i < 4; ++i) {
        int idx = tid + i * 256;
        int r = idx >> 4, cc = idx & 15;
        *(uint4*)((char*)Qs + r * 272 + cc * 16) =
            *(const uint4*)(c + (size_t)(qt * 64 + r) * (3 * DMODEL) + h * HDIM + cc * 8);
    }
    rowpat[tid] = (float)(tid >> 4);
    if (tid < 64) { mrow[tid] = -1e30f; lrow[tid] = 0.0f; }
    __syncthreads();

    wmma::fragment<wmma::accumulator, 16, 16, 16, float> rowf;
    wmma::load_matrix_sync(rowf, rowpat, 16, wmma::mem_row_major);
    int rowid[8];
    #pragma unroll
    for (int e = 0; e < 8; ++e) rowid[e] = (int)rowf.x[e];

    wmma::fragment<wmma::accumulator, 16, 16, 16, float> of[4];
    #pragma unroll
    for (int j = 0; j < 4; ++j) wmma::fill_fragment(of[j], 0.0f);

    const float scale = 0.022097086912079608f;  // 1/sqrt(2048)
    const int srow = tid >> 2, sq = tid & 3;

    for (int j = 0; j <= qt; ++j) {
        if (j < qt) { load_kv((j + 1) & 1, j + 1); CP_COMMIT(); CP_WAIT(1); }
        else        { CP_WAIT(0); }
        __syncthreads();

        const __half* Ks = (const __half*)(smg + OFF_K + (j & 1) * 17408);
        const __half* Vs = (const __half*)(smg + OFF_V + (j & 1) * 17408);

        // S = Q @ K^T : each warp 16x32
        {
            wmma::fragment<wmma::accumulator, 16, 16, 16, float> sf[2];
            wmma::fill_fragment(sf[0], 0.0f);
            wmma::fill_fragment(sf[1], 0.0f);
            #pragma unroll
            for (int ks = 0; ks < 8; ++ks) {
                wmma::fragment<wmma::matrix_a, 16, 16, 16, __half, wmma::row_major> af;
                wmma::load_matrix_sync(af, Qs + (wm * 16) * QLDH + ks * 16, QLDH);
                #pragma unroll
                for (int jj = 0; jj < 2; ++jj) {
                    wmma::fragment<wmma::matrix_b, 16, 16, 16, __half, wmma::col_major> bf;
                    wmma::load_matrix_sync(bf, Ks + (wn * 32 + jj * 16) * QLDH + ks * 16, QLDH);
                    wmma::mma_sync(sf[jj], af, bf, sf[jj]);
                }
            }
            #pragma unroll
            for (int jj = 0; jj < 2; ++jj)
                wmma::store_matrix_sync(S + (wm * 16) * SLDF + wn * 32 + jj * 16,
                                        sf[jj], SLDF, wmma::mem_row_major);
        }
        __syncthreads();

        // online softmax: 4 threads/row. Reads of S complete before the quad
        // shuffle; P writes (aliased onto S, same row) happen after it.
        {
            const bool diag = (j == qt);
            float m_old = mrow[srow];
            float mx = m_old;
            float sv[16];
            #pragma unroll
            for (int k = 0; k < 16; ++k) {
                int kcol = sq * 16 + k;
                float v = S[srow * SLDF + kcol] * scale;
                if (diag && kcol > srow) v = -1e30f;
                sv[k] = v;
                mx = fmaxf(mx, v);
            }
            mx = fmaxf(mx, __shfl_xor_sync(0xffffffffu, mx, 1));
            mx = fmaxf(mx, __shfl_xor_sync(0xffffffffu, mx, 2));
            float sum = 0.0f;
            #pragma unroll
            for (int k = 0; k < 16; ++k) {
                float p = __expf(sv[k] - mx);
                sum += p;
                P[srow * PLDH + sq * 16 + k] = __float2half_rn(p);
            }
            sum += __shfl_xor_sync(0xffffffffu, sum, 1);
            sum += __shfl_xor_sync(0xffffffffu, sum, 2);
            if (sq == 0) {
                float alpha = __expf(m_old - mx);
                mrow[srow] = mx;
                lrow[srow] = lrow[srow] * alpha + sum;
                arow[srow] = alpha;
            }
        }
        __syncthreads();

        #pragma unroll
        for (int f = 0; f < 4; ++f)
            #pragma unroll
            for (int e = 0; e < 8; ++e)
                of[f].x[e] *= arow[wm * 16 + rowid[e]];

        #pragma unroll
        for (int ks = 0; ks < 4; ++ks) {
            wmma::fragment<wmma::matrix_a, 16, 16, 16, __half, wmma::row_major> pa;
            wmma::load_matrix_sync(pa, P + (wm * 16) * PLDH + ks * 16, PLDH);
            #pragma unroll
            for (int jj = 0; jj < 4; ++jj) {
                wmma::fragment<wmma::matrix_b, 16, 16, 16, __half, wmma::row_major> vb;
                wmma::load_matrix_sync(vb, Vs + (ks * 16) * QLDH + wn * 64 + jj * 16, QLDH);
                wmma::mma_sync(of[jj], pa, vb, of[jj]);
            }
        }
        __syncthreads();
    }

    float* Os = (float*)(smg + OFF_K);   // 64 x 132 fp32 staging (33792 B)
    #pragma unroll
    for (int jj = 0; jj < 4; ++jj)
        wmma::store_matrix_sync(Os + (wm * 16) * 132 + wn * 64 + jj * 16,
                                of[jj], 132, wmma::mem_row_major);
    __syncthreads();
    #pragma unroll
    for (int i = 0; i < 8; ++i) {
        int idx = tid + i * 256;
        int r = idx >> 5, c4 = idx & 31;
        float linv = 1.0f / lrow[r];
        float4 v = *(float4*)(Os + r * 132 + c4 * 4);
        __half2 p0 = __floats2half2_rn(v.x * linv, v.y * linv);
        __half2 p1 = __floats2half2_rn(v.z * linv, v.w * linv);
        uint2 u;
        u.x = *(uint32_t*)&p0;
        u.y = *(uint32_t*)&p1;
        *(uint2*)(out + (size_t)(qt * 64 + r) * DMODEL + h * HDIM + c4 * 4) = u;
    }
}

// ================= LayerNorm: one block per row, optional half copy =========
__global__ void __launch_bounds__(256)
ln_kernel(const float* __restrict__ in, const float* __restrict__ g,
          const float* __restrict__ b, float* __restrict__ out,
          __half* __restrict__ out_h)
{
    const int row = blockIdx.x;
    const int tid = threadIdx.x;
    const float4* x4 = (const float4*)(in + (size_t)row * DMODEL);

    float4 v0 = x4[tid];
    float4 v1 = x4[tid + 256];
    float s = v0.x + v0.y + v0.z + v0.w + v1.x + v1.y + v1.z + v1.w;
    float q = v0.x * v0.x + v0.y * v0.y + v0.z * v0.z + v0.w * v0.w
            + v1.x * v1.x + v1.y * v1.y + v1.z * v1.z + v1.w * v1.w;

    #pragma unroll
    for (int o = 16; o > 0; o >>= 1) {
        s += __shfl_down_sync(0xffffffffu, s, o);
        q += __shfl_down_sync(0xffffffffu, q, o);
    }
    __shared__ float rs[8], rq[8], fin[2];
    if ((tid & 31) == 0) { rs[tid >> 5] = s; rq[tid >> 5] = q; }
    __syncthreads();
    if (tid == 0) {
        float S = 0.0f, Q = 0.0f;
        #pragma unroll
        for (int i = 0; i < 8; ++i) { S += rs[i]; Q += rq[i]; }
        float mu  = S * (1.0f / DMODEL);
        float var = Q * (1.0f / DMODEL) - mu * mu;
        fin[0] = mu;
        fin[1] = rsqrtf(var + LN_EPS);
    }
    __syncthreads();
    float mu = fin[0], r = fin[1];

    float4 g0 = ((const float4*)g)[tid], g1 = ((const float4*)g)[tid + 256];
    float4 b0 = ((const float4*)b)[tid], b1 = ((const float4*)b)[tid + 256];
    float4 o0, o1;
    o0.x = (v0.x - mu) * r * g0.x + b0.x;
    o0.y = (v0.y - mu) * r * g0.y + b0.y;
    o0.z = (v0.z - mu) * r * g0.z + b0.z;
    o0.w = (v0.w - mu) * r * g0.w + b0.w;
    o1.x = (v1.x - mu) * r * g1.x + b1.x;
    o1.y = (v1.y - mu) * r * g1.y + b1.y;
    o1.z = (v1.z - mu) * r * g1.z + b1.z;
    o1.w = (v1.w - mu) * r * g1.w + b1.w;
    ((float4*)(out + (size_t)row * DMODEL))[tid]       = o0;
    ((float4*)(out + (size_t)row * DMODEL))[tid + 256] = o1;
    if (out_h) {
        __half2 a0 = __floats2half2_rn(o0.x, o0.y);
        __half2 a1 = __floats2half2_rn(o0.z, o0.w);
        __half2 a2 = __floats2half2_rn(o1.x, o1.y);
        __half2 a3 = __floats2half2_rn(o1.z, o1.w);
        uint2 u0, u1;
        u0.x = *(uint32_t*)&a0; u0.y = *(uint32_t*)&a1;
        u1.x = *(uint32_t*)&a2; u1.y = *(uint32_t*)&a3;
        ((uint2*)(out_h + (size_t)row * DMODEL))[tid]       = u0;
        ((uint2*)(out_h + (size_t)row * DMODEL))[tid + 256] = u1;
    }
}

// ================= launch ===================================================
extern "C" void kernel_launch(void* const* d_in, const int* in_sizes, int n_in,
                              void* d_out, int out_size)
{
    (void)in_sizes; (void)n_in; (void)out_size;

    const float* x     = (const float*)d_in[0];
    const float* C_w   = (const float*)d_in[1];
    const float* C_b   = (const float*)d_in[2];
    const float* lin_w = (const float*)d_in[3];
    const float* lin_b = (const float*)d_in[4];
    const float* ff1_w = (const float*)d_in[5];
    const float* ff1_b = (const float*)d_in[6];
    const float* ff2_w = (const float*)d_in[7];
    const float* ff2_b = (const float*)d_in[8];
    const float* ln1_g = (const float*)d_in[9];
    const float* ln1_b = (const float*)d_in[10];
    const float* ln2_g = (const float*)d_in[11];
    const float* ln2_b = (const float*)d_in[12];
    float* out = (float*)d_out;

    __half *c, *attn, *h1h, *ff, *xh, *Cwh, *linh, *ff1h, *ff2h;
    float *res1, *h1, *res2;
    cudaGetSymbolAddress((void**)&c,    g_c);
    cudaGetSymbolAddress((void**)&attn, g_attn);
    cudaGetSymbolAddress((void**)&res1, g_res1);
    cudaGetSymbolAddress((void**)&h1,   g_h1);
    cudaGetSymbolAddress((void**)&h1h,  g_h1h);
    cudaGetSymbolAddress((void**)&ff,   g_ff);
    cudaGetSymbolAddress((void**)&res2, g_res2);
    cudaGetSymbolAddress((void**)&xh,   g_xh);
    cudaGetSymbolAddress((void**)&Cwh,  g_Cwh);
    cudaGetSymbolAddress((void**)&linh, g_linh);
    cudaGetSymbolAddress((void**)&ff1h, g_ff1h);
    cudaGetSymbolAddress((void**)&ff2h, g_ff2h);

    cudaFuncSetAttribute((const void*)gemm_fp16<EPI_BIAS, true>,       cudaFuncAttributeMaxDynamicSharedMemorySize, GEMM_SMEM);
    cudaFuncSetAttribute((const void*)gemm_fp16<EPI_BIAS_RES, false>,  cudaFuncAttributeMaxDynamicSharedMemorySize, GEMM_SMEM);
    cudaFuncSetAttribute((const void*)gemm_fp16<EPI_BIAS_GELU, true>,  cudaFuncAttributeMaxDynamicSharedMemorySize, GEMM_SMEM);
    cudaFuncSetAttribute((const void*)attn_kernel,                     cudaFuncAttributeMaxDynamicSharedMemorySize, ATT_SMEM);

    // 0) convert inputs to half
    f2h_kernel<<<1024, 256>>>(x,     xh,   SEQ * DMODEL / 4);
    f2h_kernel<<<1024, 256>>>(C_w,   Cwh,  DMODEL * 3 * DMODEL / 4);
    f2h_kernel<<<1024, 256>>>(lin_w, linh, DMODEL * DMODEL / 4);
    f2h_kernel<<<1024, 256>>>(ff1_w, ff1h, DMODEL * INNER / 4);
    f2h_kernel<<<1024, 256>>>(ff2_w, ff2h, INNER * DMODEL / 4);

    // 1) QKV: c = half(xh @ C_w + C_b)   [2048, 6144]
    gemm_fp16<EPI_BIAS, true><<<dim3(3 * DMODEL / 128, SEQ / 128), 256, GEMM_SMEM>>>(
        xh, Cwh, C_b, nullptr, c, SEQ, 3 * DMODEL, DMODEL);

    // 2) causal attention -> attn (half), BQ=64
    attn_kernel<<<dim3(SEQ / 64, HEADS), 256, ATT_SMEM>>>(c, attn);

    // 3) res1 = x + attn @ lin_w + lin_b  (fp32)
    gemm_fp16<EPI_BIAS_RES, false><<<dim3(DMODEL / 128, SEQ / 128), 256, GEMM_SMEM>>>(
        attn, linh, lin_b, x, res1, SEQ, DMODEL, DMODEL);

    // 4) h1 = LN1(res1); h1h = half(h1)
    ln_kernel<<<SEQ, 256>>>(res1, ln1_g, ln1_b, h1, h1h);

    // 5) ff = half(gelu(h1h @ ff1_w + ff1_b))   [2048, 8192]
    gemm_fp16<EPI_BIAS_GELU, true><<<dim3(INNER / 128, SEQ / 128), 256, GEMM_SMEM>>>(
        h1h, ff1h, ff1_b, nullptr, ff, SEQ, INNER, DMODEL);

    // 6) res2 = h1 + ff @ ff2_w + ff2_b  (fp32)
    gemm_fp16<EPI_BIAS_RES, false><<<dim3(DMODEL / 128, SEQ / 128), 256, GEMM_SMEM>>>(
        ff, ff2h, ff2_b, h1, res2, SEQ, DMODEL, INNER);

    // 7) out = LN2(res2)
    ln_kernel<<<SEQ, 256>>>(res2, ln2_g, ln2_b, out, nullptr);
}